// round 9
// baseline (speedup 1.0000x reference)
#include <cuda_runtime.h>

// DEC_LO (db4-ish lowpass) literals
#define D0 (-0.010597401784997278f)
#define D1 ( 0.032883011666982945f)
#define D2 ( 0.030841381835986965f)
#define D3 (-0.18703481171888114f)
#define D4 (-0.02798376941698385f)
#define D5 ( 0.6308807679295904f)
#define D6 ( 0.7148465705525415f)
#define D7 ( 0.23037781330885523f)

namespace {
constexpr int NT     = 512;      // threads per CTA
constexpr int ROWLEN = 32768;

// level lengths (derived exactly from reference padding math)
constexpr int L2N = 8197;   // lo2 (lo1 never materialized; folded into 22-tap filter)
constexpr int L3N = 4102;
constexpr int L4N = 2054;

constexpr int HALO  = 8;
constexpr int BCAP  = 8198;      // max content per buffer (t2 = 8198)

// Two ping-pong buffers with 8-float zeroed halos. Data offsets multiple of 4
// floats (16 B) so float4 smem stores are aligned.
constexpr int A_OFF = HALO;                         // 8
constexpr int B_OFF = 8224;                         // 16B-aligned, >= 8+8198+16
constexpr int SMEM_FLOATS = B_OFF + BCAP + HALO;    // 16430
constexpr int SMEM_BYTES  = SMEM_FLOATS * (int)sizeof(float); // 65720 B -> 3 CTAs/SM

// h[s] = DEC_LO[7-s] (analysis filter, reversed)
__host__ __device__ constexpr float Hc(int s) {
    return (s == 0) ? D7 : (s == 1) ? D6 : (s == 2) ? D5 : (s == 3) ? D4
         : (s == 4) ? D3 : (s == 5) ? D2 : (s == 6) ? D1 : D0;
}
// Composite 22-tap filter: c[u] = sum_s h[s]*h[u-2s].  lo2[j] = sum_u c[u]*x[4j+u-18]
__host__ __device__ constexpr float Cc(int u) {
    float acc = 0.f;
    for (int s = 0; s < 8; ++s) {
        int k = u - 2 * s;
        if (k >= 0 && k < 8) acc += Hc(s) * Hc(k);
    }
    return acc;
}
}

// Analysis step in smem, PAIRED outputs: out[j0], out[j0+1] from in[2j0-6 .. 2j0+3]
// (10 floats = 5 aligned float2). `in` has zeroed 8-float halos both sides.
// Also zeroes the upper halo of `out` for the next stage. Output lengths at
// every call site (4102, 2054) are even, so pairs are always complete.
__device__ __forceinline__ void afb_smem(const float* __restrict__ in, int N,
                                         float* __restrict__ out)
{
    const int outN  = (N + 7) >> 1;
    const int pairs = (outN + 1) >> 1;
    for (int p = threadIdx.x; p < pairs; p += NT) {
        const int j0 = 2 * p;
        const float2* p2 = reinterpret_cast<const float2*>(in + 2 * j0 - 6);
        float2 v0 = p2[0], v1 = p2[1], v2 = p2[2], v3 = p2[3], v4 = p2[4];
        float s0, s1;
        s0 = fmaf(Hc(0), v0.x, fmaf(Hc(1), v0.y, fmaf(Hc(2), v1.x, fmaf(Hc(3), v1.y,
             fmaf(Hc(4), v2.x, fmaf(Hc(5), v2.y, fmaf(Hc(6), v3.x, Hc(7) * v3.y)))))));
        s1 = fmaf(Hc(0), v1.x, fmaf(Hc(1), v1.y, fmaf(Hc(2), v2.x, fmaf(Hc(3), v2.y,
             fmaf(Hc(4), v3.x, fmaf(Hc(5), v3.y, fmaf(Hc(6), v4.x, Hc(7) * v4.y)))))));
        if (j0 + 1 < outN) {
            *reinterpret_cast<float2*>(out + j0) = make_float2(s0, s1);
        } else {
            out[j0] = s0;
        }
    }
    if (threadIdx.x < HALO) out[outN + threadIdx.x] = 0.f;
}

// Synthesis step in smem, PAIRED i: outputs out[2i0..2i0+3] from in[i0..i0+4]
// (i0 even -> 2 aligned float2 + 1 scalar; float4 store). Tail (odd n) writes
// a float2; its in[i0+4] read lands in the zeroed halo.
__device__ __forceinline__ void sfb_smem(const float* __restrict__ in, int M,
                                         float* __restrict__ out)
{
    const int n = M - 3;               // valid i < n
    const int pairs = (n + 1) >> 1;
    for (int p = threadIdx.x; p < pairs; p += NT) {
        const int i0 = 2 * p;
        float2 u0 = *reinterpret_cast<const float2*>(in + i0);
        float2 u1 = *reinterpret_cast<const float2*>(in + i0 + 2);
        float  w4 = in[i0 + 4];
        float e0 = fmaf(D1, u0.x, fmaf(D3, u0.y, fmaf(D5, u1.x, D7 * u1.y)));
        float o0 = fmaf(D0, u0.x, fmaf(D2, u0.y, fmaf(D4, u1.x, D6 * u1.y)));
        if (i0 + 1 < n) {
            float e1 = fmaf(D1, u0.y, fmaf(D3, u1.x, fmaf(D5, u1.y, D7 * w4)));
            float o1 = fmaf(D0, u0.y, fmaf(D2, u1.x, fmaf(D4, u1.y, D6 * w4)));
            *reinterpret_cast<float4*>(out + 2 * i0) = make_float4(e0, o0, e1, o1);
        } else {
            *reinterpret_cast<float2*>(out + 2 * i0) = make_float2(e0, o0);
        }
    }
}

__global__ __launch_bounds__(NT, 3)
void WT_series_decomp_kernel(const float* __restrict__ x,
                             float* __restrict__ season,
                             float* __restrict__ trend)
{
    extern __shared__ float smem[];
    float* A = smem + A_OFF;
    float* B = smem + B_OFF;
    const int tid = threadIdx.x;
    const float* xr = x + (size_t)blockIdx.x * ROWLEN;

    // zero the (never-rewritten) lower halos once
    if (tid < HALO) { A[tid - HALO] = 0.f; B[tid - HALO] = 0.f; }

    // ---- Fused analysis levels 1+2 (22-tap, decimate-4): x -> lo2 in A ----
    // Paired outputs j0, j0+1; interior path: window w[0..27] = x[4(j0-5)..+27]
    // via 7 aligned float4 loads; out j0 taps c[u]*w[u+2], out j0+1 taps c[u]*w[u+6].
    {
        const float4* x4 = reinterpret_cast<const float4*>(xr);
        const int pairs = (L2N + 1) >> 1;   // 4099
        for (int p = tid; p < pairs; p += NT) {
            const int j0 = 2 * p;
            if (j0 >= 6 && j0 <= 8190) {
                float s0 = 0.f, s1 = 0.f;
#pragma unroll
                for (int q = 0; q < 7; ++q) {
                    float4 v = __ldg(&x4[j0 - 5 + q]);
                    const float vv[4] = {v.x, v.y, v.z, v.w};
#pragma unroll
                    for (int m = 0; m < 4; ++m) {
                        const int u0 = 4 * q + m - 2;
                        const int u1 = 4 * q + m - 6;
                        if (u0 >= 0 && u0 < 22) s0 = fmaf(Cc(u0), vv[m], s0);
                        if (u1 >= 0 && u1 < 22) s1 = fmaf(Cc(u1), vv[m], s1);
                    }
                }
                *reinterpret_cast<float2*>(A + j0) = make_float2(s0, s1);
            } else {
                // boundary: scalar with bounds checks (zero-padded x)
#pragma unroll 1
                for (int jj = j0; jj < j0 + 2 && jj < L2N; ++jj) {
                    float s = 0.f;
#pragma unroll
                    for (int u = 0; u < 22; ++u) {
                        int idx = 4 * jj + u - 18;
                        float v = ((unsigned)idx < (unsigned)ROWLEN) ? xr[idx] : 0.f;
                        s = fmaf(Cc(u), v, s);
                    }
                    A[jj] = s;
                }
            }
        }
        if (tid < HALO) A[L2N + tid] = 0.f;
    }
    __syncthreads();

    afb_smem(A, L2N, B);  __syncthreads();   // lo3: 4102 in B
    afb_smem(B, L3N, A);  __syncthreads();   // lo4: 2054 in A

    sfb_smem(A, L4N, B);  __syncthreads();   // t1: 4102 in B
    sfb_smem(B, L3N, A);  __syncthreads();   // t2: 8198 in A (use first 8197)

    // ---- Fused final two synthesis stages (t2 -> t3 -> out, t3 in registers),
    //      PAIRED quads: T[i0..i0+6] -> out[4i0..4i0+7]; season = x - trend ----
    {
        const float4* x4  = reinterpret_cast<const float4*>(xr);
        float4* tr4 = reinterpret_cast<float4*>(trend  + (size_t)blockIdx.x * ROWLEN);
        float4* se4 = reinterpret_cast<float4*>(season + (size_t)blockIdx.x * ROWLEN);
        const float* T = A;  // t2
        for (int i0 = 2 * tid; i0 < ROWLEN / 4; i0 += 2 * NT) {   // 8 iterations
            float2 t0 = *reinterpret_cast<const float2*>(T + i0);
            float2 t1 = *reinterpret_cast<const float2*>(T + i0 + 2);
            float2 t2 = *reinterpret_cast<const float2*>(T + i0 + 4);
            float  t6 = T[i0 + 6];
            const float a0 = t0.x, a1 = t0.y, a2 = t1.x, a3 = t1.y,
                        a4 = t2.x, a5 = t2.y, a6 = t6;
            // t3 values 2i0 .. 2i0+6 on the fly
            float e0 = fmaf(D1, a0, fmaf(D3, a1, fmaf(D5, a2, D7 * a3)));
            float o0 = fmaf(D0, a0, fmaf(D2, a1, fmaf(D4, a2, D6 * a3)));
            float e1 = fmaf(D1, a1, fmaf(D3, a2, fmaf(D5, a3, D7 * a4)));
            float o1 = fmaf(D0, a1, fmaf(D2, a2, fmaf(D4, a3, D6 * a4)));
            float e2 = fmaf(D1, a2, fmaf(D3, a3, fmaf(D5, a4, D7 * a5)));
            float o2 = fmaf(D0, a2, fmaf(D2, a3, fmaf(D4, a4, D6 * a5)));
            float e3 = fmaf(D1, a3, fmaf(D3, a4, fmaf(D5, a5, D7 * a6)));
            // quad i0 -> out[4i0..4i0+3]
            float y0 = fmaf(D1, e0, fmaf(D3, o0, fmaf(D5, e1, D7 * o1)));
            float y1 = fmaf(D0, e0, fmaf(D2, o0, fmaf(D4, e1, D6 * o1)));
            float y2 = fmaf(D1, o0, fmaf(D3, e1, fmaf(D5, o1, D7 * e2)));
            float y3 = fmaf(D0, o0, fmaf(D2, e1, fmaf(D4, o1, D6 * e2)));
            // quad i0+1 -> out[4i0+4..4i0+7]
            float z0 = fmaf(D1, e1, fmaf(D3, o1, fmaf(D5, e2, D7 * o2)));
            float z1 = fmaf(D0, e1, fmaf(D2, o1, fmaf(D4, e2, D6 * o2)));
            float z2 = fmaf(D1, o1, fmaf(D3, e2, fmaf(D5, o2, D7 * e3)));
            float z3 = fmaf(D0, o1, fmaf(D2, e2, fmaf(D4, o2, D6 * e3)));
            float4 xv0 = __ldg(&x4[i0]);
            float4 xv1 = __ldg(&x4[i0 + 1]);
            tr4[i0]     = make_float4(y0, y1, y2, y3);
            tr4[i0 + 1] = make_float4(z0, z1, z2, z3);
            se4[i0]     = make_float4(xv0.x - y0, xv0.y - y1, xv0.z - y2, xv0.w - y3);
            se4[i0 + 1] = make_float4(xv1.x - z0, xv1.y - z1, xv1.z - z2, xv1.w - z3);
        }
    }
}

extern "C" void kernel_launch(void* const* d_in, const int* in_sizes, int n_in,
                              void* d_out, int out_size)
{
    const float* x = (const float*)d_in[0];
    const int rows = in_sizes[0] / ROWLEN;   // 32 * 16 = 512 for this shape
    float* out = (float*)d_out;
    float* season = out;                                  // tuple element 0
    float* trend  = out + (size_t)rows * ROWLEN;          // tuple element 1

    cudaFuncSetAttribute(WT_series_decomp_kernel,
                         cudaFuncAttributeMaxDynamicSharedMemorySize, SMEM_BYTES);
    WT_series_decomp_kernel<<<rows, NT, SMEM_BYTES>>>(x, season, trend);
}

// round 10
// speedup vs baseline: 1.1461x; 1.1461x over previous
#include <cuda_runtime.h>

// DEC_LO (db4-ish lowpass) literals
#define D0 (-0.010597401784997278f)
#define D1 ( 0.032883011666982945f)
#define D2 ( 0.030841381835986965f)
#define D3 (-0.18703481171888114f)
#define D4 (-0.02798376941698385f)
#define D5 ( 0.6308807679295904f)
#define D6 ( 0.7148465705525415f)
#define D7 ( 0.23037781330885523f)

namespace {
constexpr int NT     = 512;      // threads per CTA
constexpr int ROWLEN = 32768;

// level lengths (derived exactly from reference padding math)
constexpr int L2N = 8197;   // lo2 (lo1 folded into composite 22-tap filter)
constexpr int L3N = 4102;
constexpr int L4N = 2054;

constexpr int HALO = 8;
constexpr int ACAP = 8198;       // A holds lo2 (8197), lo4 (2054), t2 (8198)
constexpr int BCAP = 4110;       // B holds lo3 (4102), t1 (4102) + 8 halo

constexpr int A_OFF = HALO;                          // 8
constexpr int B_OFF = A_OFF + ACAP + HALO + HALO;    // 8222 -> even; round to 8224
constexpr int B_OFF_AL = 8224;                       // keep 16B alignment headroom
constexpr int SMEM_FLOATS = B_OFF_AL + BCAP;         // 12334
constexpr int SMEM_BYTES  = SMEM_FLOATS * (int)sizeof(float);  // 49336 B -> 3 CTAs/SM

// h[s] = DEC_LO[7-s] (analysis filter, reversed)
__host__ __device__ constexpr float Hc(int s) {
    return (s == 0) ? D7 : (s == 1) ? D6 : (s == 2) ? D5 : (s == 3) ? D4
         : (s == 4) ? D3 : (s == 5) ? D2 : (s == 6) ? D1 : D0;
}
// Composite 22-tap filter: c[u] = sum_s h[s]*h[u-2s].  lo2[j] = sum_u c[u]*x[4j+u-18]
__host__ __device__ constexpr float Cc(int u) {
    float acc = 0.f;
    for (int s = 0; s < 8; ++s) {
        int k = u - 2 * s;
        if (k >= 0 && k < 8) acc += Hc(s) * Hc(k);
    }
    return acc;
}
}

// Analysis step in smem: ONE output per thread, lane-contiguous j.
// out[j] = sum_t h[t] * in[2j + t - 6]; window = 4 aligned float2 -> LDS.64 at
// 8B lane stride = fully contiguous, conflict-free. `in` has zeroed 8-float
// halos both sides; zeroes the upper halo of `out` for the next stage.
__device__ __forceinline__ void afb_smem(const float* __restrict__ in, int N,
                                         float* __restrict__ out)
{
    const int outN = (N + 7) >> 1;
    for (int j = threadIdx.x; j < outN; j += NT) {
        const float2* p2 = reinterpret_cast<const float2*>(in + 2 * j - 6);
        float2 v0 = p2[0], v1 = p2[1], v2 = p2[2], v3 = p2[3];
        float s;
        s = fmaf(Hc(0), v0.x, fmaf(Hc(1), v0.y, fmaf(Hc(2), v1.x, fmaf(Hc(3), v1.y,
            fmaf(Hc(4), v2.x, fmaf(Hc(5), v2.y, fmaf(Hc(6), v3.x, Hc(7) * v3.y)))))));
        out[j] = s;
    }
    if (threadIdx.x < HALO) out[outN + threadIdx.x] = 0.f;
}

// Synthesis step in smem: ONE i per thread, lane-contiguous. Scalar LDS
// (4B lane stride, conflict-free), float2 store (8B lane stride, contiguous).
// out[2i] = D1*in[i]+D3*in[i+1]+D5*in[i+2]+D7*in[i+3]; out[2i+1] uses D0,D2,D4,D6.
__device__ __forceinline__ void sfb_smem(const float* __restrict__ in, int M,
                                         float* __restrict__ out)
{
    const int n = M - 3;
    float2* o2 = reinterpret_cast<float2*>(out);
    for (int i = threadIdx.x; i < n; i += NT) {
        float a = in[i], b = in[i + 1], c = in[i + 2], d = in[i + 3];
        float e = fmaf(D1, a, fmaf(D3, b, fmaf(D5, c, D7 * d)));
        float o = fmaf(D0, a, fmaf(D2, b, fmaf(D4, c, D6 * d)));
        o2[i] = make_float2(e, o);
    }
}

__global__ __launch_bounds__(NT, 3)
void WT_series_decomp_kernel(const float* __restrict__ x,
                             float* __restrict__ season,
                             float* __restrict__ trend)
{
    extern __shared__ float smem[];
    float* A = smem + A_OFF;
    float* B = smem + B_OFF_AL;
    const int tid = threadIdx.x;
    const float* xr = x + (size_t)blockIdx.x * ROWLEN;

    // zero the (never-rewritten) lower halos once
    if (tid < HALO) { A[tid - HALO] = 0.f; B[tid - HALO] = 0.f; }

    // ---- Fused analysis levels 1+2 (22-tap, decimate-4): x -> lo2 in A ----
    // ONE output per thread, lane-contiguous j. Interior: window x[4j-18..4j+3]
    // is contained in float4 indices [j-5, j] -> 6 LDG.128, 16B lane stride =
    // fully contiguous 512B per warp (4 wavefronts/instr).
    {
        const float4* x4 = reinterpret_cast<const float4*>(xr);
        for (int j = tid; j < L2N; j += NT) {
            if (j >= 5 && j <= 8191) {
                float s = 0.f;
#pragma unroll
                for (int q = 0; q < 6; ++q) {
                    float4 v = __ldg(&x4[j - 5 + q]);
                    const float vv[4] = {v.x, v.y, v.z, v.w};
#pragma unroll
                    for (int m = 0; m < 4; ++m) {
                        const int u = 4 * q + m - 2;   // tap index into c[0..21]
                        if (u >= 0 && u < 22) s = fmaf(Cc(u), vv[m], s);
                    }
                }
                A[j] = s;
            } else {
                // boundary: scalar with bounds checks (zero-padded x)
                float s = 0.f;
#pragma unroll
                for (int u = 0; u < 22; ++u) {
                    int idx = 4 * j + u - 18;
                    float v = ((unsigned)idx < (unsigned)ROWLEN) ? xr[idx] : 0.f;
                    s = fmaf(Cc(u), v, s);
                }
                A[j] = s;
            }
        }
        if (tid < HALO) A[L2N + tid] = 0.f;
    }
    __syncthreads();

    afb_smem(A, L2N, B);  __syncthreads();   // lo3: 4102 in B
    afb_smem(B, L3N, A);  __syncthreads();   // lo4: 2054 in A

    sfb_smem(A, L4N, B);  __syncthreads();   // t1: 4102 in B
    sfb_smem(B, L3N, A);  __syncthreads();   // t2: 8198 in A (use first 8197)

    // ---- Fused final two synthesis stages (t2 -> t3 -> out, t3 in registers),
    //      ONE quad per thread-iteration: T[i..i+5] -> out[4i..4i+3];
    //      season = x - trend, float4 global I/O ----
    {
        const float4* x4  = reinterpret_cast<const float4*>(xr);
        float4* tr4 = reinterpret_cast<float4*>(trend  + (size_t)blockIdx.x * ROWLEN);
        float4* se4 = reinterpret_cast<float4*>(season + (size_t)blockIdx.x * ROWLEN);
        const float* T = A;  // t2
        for (int i = tid; i < ROWLEN / 4; i += NT) {   // 16 iterations
            float a0 = T[i],     a1 = T[i + 1], a2 = T[i + 2];
            float a3 = T[i + 3], a4 = T[i + 4], a5 = T[i + 5];
            // t3[2i..2i+4] on the fly
            float e0 = fmaf(D1, a0, fmaf(D3, a1, fmaf(D5, a2, D7 * a3)));
            float o0 = fmaf(D0, a0, fmaf(D2, a1, fmaf(D4, a2, D6 * a3)));
            float e1 = fmaf(D1, a1, fmaf(D3, a2, fmaf(D5, a3, D7 * a4)));
            float o1 = fmaf(D0, a1, fmaf(D2, a2, fmaf(D4, a3, D6 * a4)));
            float e2 = fmaf(D1, a2, fmaf(D3, a3, fmaf(D5, a4, D7 * a5)));
            // final synthesis from t3
            float y0 = fmaf(D1, e0, fmaf(D3, o0, fmaf(D5, e1, D7 * o1)));  // out[4i]
            float y1 = fmaf(D0, e0, fmaf(D2, o0, fmaf(D4, e1, D6 * o1)));  // out[4i+1]
            float y2 = fmaf(D1, o0, fmaf(D3, e1, fmaf(D5, o1, D7 * e2)));  // out[4i+2]
            float y3 = fmaf(D0, o0, fmaf(D2, e1, fmaf(D4, o1, D6 * e2)));  // out[4i+3]
            float4 xv = __ldg(&x4[i]);
            tr4[i] = make_float4(y0, y1, y2, y3);
            se4[i] = make_float4(xv.x - y0, xv.y - y1, xv.z - y2, xv.w - y3);
        }
    }
}

extern "C" void kernel_launch(void* const* d_in, const int* in_sizes, int n_in,
                              void* d_out, int out_size)
{
    const float* x = (const float*)d_in[0];
    const int rows = in_sizes[0] / ROWLEN;   // 32 * 16 = 512 for this shape
    float* out = (float*)d_out;
    float* season = out;                                  // tuple element 0
    float* trend  = out + (size_t)rows * ROWLEN;          // tuple element 1

    cudaFuncSetAttribute(WT_series_decomp_kernel,
                         cudaFuncAttributeMaxDynamicSharedMemorySize, SMEM_BYTES);
    WT_series_decomp_kernel<<<rows, NT, SMEM_BYTES>>>(x, season, trend);
}

// round 15
// speedup vs baseline: 1.2824x; 1.1189x over previous
#include <cuda_runtime.h>

// DEC_LO (db4-ish lowpass) literals
#define D0 (-0.010597401784997278f)
#define D1 ( 0.032883011666982945f)
#define D2 ( 0.030841381835986965f)
#define D3 (-0.18703481171888114f)
#define D4 (-0.02798376941698385f)
#define D5 ( 0.6308807679295904f)
#define D6 ( 0.7148465705525415f)
#define D7 ( 0.23037781330885523f)

namespace {
constexpr int NT     = 512;      // threads per CTA
constexpr int ROWLEN = 32768;

// level lengths (derived exactly from reference padding math)
constexpr int L2N = 8197;   // lo2 (levels 1+2 fused into one 22-tap filter)
constexpr int L4N = 2054;   // lo4 (levels 3+4 fused into one 22-tap filter)

// A: lower halo 20 (stage-3 float4 reads reach lo2[-20]), data up to t2[8199],
//    upper zeros lo2[8197..8216] for stage-3 reads (max index 8215).
constexpr int A_OFF = 20;                      // A_OFF % 4 == 0 -> aligned float4
constexpr int B_OFF = 8240;                    // 16B-aligned, past A extent (8237)
constexpr int SMEM_FLOATS = B_OFF + 2064;      // B: lo4 2054 + 8 halo, rounded
constexpr int SMEM_BYTES  = SMEM_FLOATS * (int)sizeof(float);  // 41216 B -> 4 CTAs/SM

// h[s] = DEC_LO[7-s] (analysis filter, reversed)
__host__ __device__ constexpr float Hc(int s) {
    return (s == 0) ? D7 : (s == 1) ? D6 : (s == 2) ? D5 : (s == 3) ? D4
         : (s == 4) ? D3 : (s == 5) ? D2 : (s == 6) ? D1 : D0;
}
// Composite 22-tap filter: c[u] = sum_s h[s]*h[u-2s].
// One decimate-4 application == two decimate-2 lowpass levels (exact, incl.
// boundaries: out-of-range intermediate windows map fully out of input range).
__host__ __device__ constexpr float Cc(int u) {
    float acc = 0.f;
    for (int s = 0; s < 8; ++s) {
        int k = u - 2 * s;
        if (k >= 0 && k < 8) acc += Hc(s) * Hc(k);
    }
    return acc;
}
}

__global__ __launch_bounds__(NT, 4)
void WT_series_decomp_kernel(const float* __restrict__ x,
                             float* __restrict__ season,
                             float* __restrict__ trend)
{
    extern __shared__ float smem[];
    float* A = smem + A_OFF;   // lo2, later t2
    float* B = smem + B_OFF;   // lo4
    const int tid = threadIdx.x;
    const float* xr = x + (size_t)blockIdx.x * ROWLEN;

    // zero A's lower halo (stage-3 reads lo2[-20..-1]); B needs no lower halo
    if (tid < 20) A[tid - 20] = 0.f;

    // ---- Stage 1: fused analysis levels 1+2 (22-tap, decimate-4): x -> lo2 in A
    // ONE output per thread, lane-contiguous j. Interior: window x[4j-18..4j+3]
    // inside float4 indices [j-5, j] -> 6 LDG.128, 16B lane stride = contiguous.
    {
        const float4* x4 = reinterpret_cast<const float4*>(xr);
        for (int j = tid; j < L2N; j += NT) {
            if (j >= 5 && j <= 8191) {
                float s = 0.f;
#pragma unroll
                for (int q = 0; q < 6; ++q) {
                    float4 v = __ldg(&x4[j - 5 + q]);
                    const float vv[4] = {v.x, v.y, v.z, v.w};
#pragma unroll
                    for (int m = 0; m < 4; ++m) {
                        const int u = 4 * q + m - 2;   // tap index into c[0..21]
                        if (u >= 0 && u < 22) s = fmaf(Cc(u), vv[m], s);
                    }
                }
                A[j] = s;
            } else {
                // boundary: scalar with bounds checks (zero-padded x)
                float s = 0.f;
#pragma unroll
                for (int u = 0; u < 22; ++u) {
                    int idx = 4 * j + u - 18;
                    float v = ((unsigned)idx < (unsigned)ROWLEN) ? xr[idx] : 0.f;
                    s = fmaf(Cc(u), v, s);
                }
                A[j] = s;
            }
        }
        if (tid < 20) A[L2N + tid] = 0.f;   // zeros lo2[8197..8216]
    }
    __syncthreads();

    // ---- Stage 2: fused analysis levels 3+4 (same 22-tap, decimate-4):
    //      lo4[j] = sum_u c[u] * lo2[4j+u-18], j in [0,2054). Halos make this
    //      branch-free: 6 aligned LDS.128 per output (A_OFF%4==0, base 4j-20).
    {
        for (int j = tid; j < L4N; j += NT) {
            const float4* a4 = reinterpret_cast<const float4*>(A + 4 * j - 20);
            float s = 0.f;
#pragma unroll
            for (int q = 0; q < 6; ++q) {
                float4 v = a4[q];
                const float vv[4] = {v.x, v.y, v.z, v.w};
#pragma unroll
                for (int m = 0; m < 4; ++m) {
                    const int u = 4 * q + m - 2;       // e in [0,23] -> u in [-2,21]
                    if (u >= 0 && u < 22) s = fmaf(Cc(u), vv[m], s);
                }
            }
            B[j] = s;
        }
        if (tid < 8) B[L4N + tid] = 0.f;    // upper halo for stage-3 tail reads
    }
    __syncthreads();

    // ---- Stage 3: fused synthesis levels 1+2 (lo4 -> t1 in regs -> t2 in A).
    //      Quad p: t2[4p..4p+3] from lo4[p..p+5]; p in [0,2050). The p=2049
    //      tail writes t2[8198..8199] (garbage, never read; reads hit halo).
    {
        for (int p = tid; p < 2050; p += NT) {
            float b0 = B[p],     b1 = B[p + 1], b2 = B[p + 2];
            float b3 = B[p + 3], b4 = B[p + 4], b5 = B[p + 5];
            // t1[2p..2p+4] on the fly
            float e0 = fmaf(D1, b0, fmaf(D3, b1, fmaf(D5, b2, D7 * b3)));
            float o0 = fmaf(D0, b0, fmaf(D2, b1, fmaf(D4, b2, D6 * b3)));
            float e1 = fmaf(D1, b1, fmaf(D3, b2, fmaf(D5, b3, D7 * b4)));
            float o1 = fmaf(D0, b1, fmaf(D2, b2, fmaf(D4, b3, D6 * b4)));
            float e2 = fmaf(D1, b2, fmaf(D3, b3, fmaf(D5, b4, D7 * b5)));
            // t2 quad from t1
            float y0 = fmaf(D1, e0, fmaf(D3, o0, fmaf(D5, e1, D7 * o1)));
            float y1 = fmaf(D0, e0, fmaf(D2, o0, fmaf(D4, e1, D6 * o1)));
            float y2 = fmaf(D1, o0, fmaf(D3, e1, fmaf(D5, o1, D7 * e2)));
            float y3 = fmaf(D0, o0, fmaf(D2, e1, fmaf(D4, o1, D6 * e2)));
            *reinterpret_cast<float4*>(A + 4 * p) = make_float4(y0, y1, y2, y3);
        }
    }
    __syncthreads();

    // ---- Stage 4: fused synthesis levels 3+4 (t2 -> t3 in regs -> out),
    //      + season = x - trend, float4 global I/O. Reads T[i..i+5], i<8192
    //      (max index 8196 < 8197 valid t2 extent).
    {
        const float4* x4  = reinterpret_cast<const float4*>(xr);
        float4* tr4 = reinterpret_cast<float4*>(trend  + (size_t)blockIdx.x * ROWLEN);
        float4* se4 = reinterpret_cast<float4*>(season + (size_t)blockIdx.x * ROWLEN);
        const float* T = A;  // t2
        for (int i = tid; i < ROWLEN / 4; i += NT) {   // 16 iterations
            float a0 = T[i],     a1 = T[i + 1], a2 = T[i + 2];
            float a3 = T[i + 3], a4 = T[i + 4], a5 = T[i + 5];
            // t3[2i..2i+4] on the fly
            float e0 = fmaf(D1, a0, fmaf(D3, a1, fmaf(D5, a2, D7 * a3)));
            float o0 = fmaf(D0, a0, fmaf(D2, a1, fmaf(D4, a2, D6 * a3)));
            float e1 = fmaf(D1, a1, fmaf(D3, a2, fmaf(D5, a3, D7 * a4)));
            float o1 = fmaf(D0, a1, fmaf(D2, a2, fmaf(D4, a3, D6 * a4)));
            float e2 = fmaf(D1, a2, fmaf(D3, a3, fmaf(D5, a4, D7 * a5)));
            // out quad from t3
            float y0 = fmaf(D1, e0, fmaf(D3, o0, fmaf(D5, e1, D7 * o1)));
            float y1 = fmaf(D0, e0, fmaf(D2, o0, fmaf(D4, e1, D6 * o1)));
            float y2 = fmaf(D1, o0, fmaf(D3, e1, fmaf(D5, o1, D7 * e2)));
            float y3 = fmaf(D0, o0, fmaf(D2, e1, fmaf(D4, o1, D6 * e2)));
            float4 xv = __ldg(&x4[i]);
            tr4[i] = make_float4(y0, y1, y2, y3);
            se4[i] = make_float4(xv.x - y0, xv.y - y1, xv.z - y2, xv.w - y3);
        }
    }
}

extern "C" void kernel_launch(void* const* d_in, const int* in_sizes, int n_in,
                              void* d_out, int out_size)
{
    const float* x = (const float*)d_in[0];
    const int rows = in_sizes[0] / ROWLEN;   // 32 * 16 = 512 for this shape
    float* out = (float*)d_out;
    float* season = out;                                  // tuple element 0
    float* trend  = out + (size_t)rows * ROWLEN;          // tuple element 1

    cudaFuncSetAttribute(WT_series_decomp_kernel,
                         cudaFuncAttributeMaxDynamicSharedMemorySize, SMEM_BYTES);
    WT_series_decomp_kernel<<<rows, NT, SMEM_BYTES>>>(x, season, trend);
}

// round 17
// speedup vs baseline: 1.3009x; 1.0144x over previous
#include <cuda_runtime.h>

// DEC_LO (db4-ish lowpass) literals
#define D0 (-0.010597401784997278f)
#define D1 ( 0.032883011666982945f)
#define D2 ( 0.030841381835986965f)
#define D3 (-0.18703481171888114f)
#define D4 (-0.02798376941698385f)
#define D5 ( 0.6308807679295904f)
#define D6 ( 0.7148465705525415f)
#define D7 ( 0.23037781330885523f)

namespace {
constexpr int NTT    = 256;      // threads per CTA
constexpr int ROWLEN = 32768;

// Half-row decomposition: CTA (row, h) computes out[h*16384 .. +16383].
// Receptive field: needs lo2 global [h*4096-18 .. h*4096+4123] (4142 vals),
// lo4 global [h*1024 .. h*1024+1030], t2 global [h*4096 .. h*4096+4103].
// Overlap recompute overhead ~1%.
//
// Local A buffer: lo2 at L = jg - (h*4096 - 20) (so stage-2 float4 reads are
// purely local: base A + 4*jb), later reused for t2 local [0..4103].
constexpr int A_SZ  = 4160;      // lo2 local extent (reads reach L=4143)
constexpr int B_OFF = 4160;      // 16B-aligned
constexpr int B_SZ  = 1040;      // lo4 local 1031 values
constexpr int SMEM_FLOATS = B_OFF + B_SZ;                      // 5200
constexpr int SMEM_BYTES  = SMEM_FLOATS * (int)sizeof(float);  // 20800 -> occ 8

// h[s] = DEC_LO[7-s] (analysis filter, reversed)
__host__ __device__ constexpr float Hc(int s) {
    return (s == 0) ? D7 : (s == 1) ? D6 : (s == 2) ? D5 : (s == 3) ? D4
         : (s == 4) ? D3 : (s == 5) ? D2 : (s == 6) ? D1 : D0;
}
// Composite 22-tap filter: c[u] = sum_s h[s]*h[u-2s].
// One decimate-4 application == two decimate-2 lowpass levels (exact incl.
// boundaries: out-of-range intermediate windows map fully out of input range).
__host__ __device__ constexpr float Cc(int u) {
    float acc = 0.f;
    for (int s = 0; s < 8; ++s) {
        int k = u - 2 * s;
        if (k >= 0 && k < 8) acc += Hc(s) * Hc(k);
    }
    return acc;
}
}

__global__ __launch_bounds__(NTT, 8)
void WT_series_decomp_kernel(const float* __restrict__ x,
                             float* __restrict__ season,
                             float* __restrict__ trend)
{
    extern __shared__ float smem[];
    float* A = smem;            // lo2 local, later t2 local
    float* B = smem + B_OFF;    // lo4 local
    const int tid = threadIdx.x;
    const int row = blockIdx.x >> 1;
    const int h   = blockIdx.x & 1;
    const float* xr = x + (size_t)row * ROWLEN;

    // Zero the A slots that stage 2 reads but stage 1 never writes.
    // h=0: writes L in [20..4143]   -> zero L [0..19].
    // h=1: writes L in [2..4120]    -> zero L [0..1] and [4121..4159].
    if (h == 0) {
        if (tid < 20) A[tid] = 0.f;
    } else {
        if (tid < 2)  A[tid] = 0.f;
        if (tid < 39) A[4121 + tid] = 0.f;
    }

    // ---- Stage 1: fused analysis levels 1+2 (22-tap, decimate-4):
    //      lo2[jg] = sum_u c[u]*x[4jg+u-18] for this half's jg range.
    //      Interior: 6 LDG.128 at 16B lane stride = fully coalesced.
    {
        const float4* x4 = reinterpret_cast<const float4*>(xr);
        const int jg0  = h ? 4078 : 0;
        const int NJ   = h ? 4119 : 4124;
        const int soff = h ? 2    : 20;      // local store offset (= jg0 - (h*4096-20))
        for (int l = tid; l < NJ; l += NTT) {
            const int jg = jg0 + l;
            float s = 0.f;
            if (jg >= 5 && jg <= 8191) {
#pragma unroll
                for (int q = 0; q < 6; ++q) {
                    float4 v = __ldg(&x4[jg - 5 + q]);
                    const float vv[4] = {v.x, v.y, v.z, v.w};
#pragma unroll
                    for (int m = 0; m < 4; ++m) {
                        const int u = 4 * q + m - 2;   // tap into c[0..21]
                        if (u >= 0 && u < 22) s = fmaf(Cc(u), vv[m], s);
                    }
                }
            } else {
                // boundary: scalar with bounds checks (zero-padded x)
#pragma unroll
                for (int u = 0; u < 22; ++u) {
                    int idx = 4 * jg + u - 18;
                    float v = ((unsigned)idx < (unsigned)ROWLEN) ? xr[idx] : 0.f;
                    s = fmaf(Cc(u), v, s);
                }
            }
            A[soff + l] = s;
        }
    }
    __syncthreads();

    // ---- Stage 2: fused analysis levels 3+4 (same 22-tap, decimate-4):
    //      lo4 local jb in [0,1031): reads A[4jb .. 4jb+23] (6 aligned LDS.128).
    //      Zero padding in A makes this exact at both global boundaries
    //      (including the implicit lo4[2054]=0 tail value for h=1, which only
    //      feeds the never-read garbage t2 tail).
    {
        for (int jb = tid; jb < 1031; jb += NTT) {
            const float4* a4 = reinterpret_cast<const float4*>(A + 4 * jb);
            float s = 0.f;
#pragma unroll
            for (int q = 0; q < 6; ++q) {
                float4 v = a4[q];
                const float vv[4] = {v.x, v.y, v.z, v.w};
#pragma unroll
                for (int m = 0; m < 4; ++m) {
                    const int u = 4 * q + m - 2;
                    if (u >= 0 && u < 22) s = fmaf(Cc(u), vv[m], s);
                }
            }
            B[jb] = s;
        }
    }
    __syncthreads();

    // ---- Stage 3: fused synthesis levels 1+2 (lo4 -> t1 in regs -> t2 in A).
    //      Quad pb in [0,1026): t2 local [4pb..4pb+3] from B[pb..pb+5].
    {
        for (int pb = tid; pb < 1026; pb += NTT) {
            float b0 = B[pb],     b1 = B[pb + 1], b2 = B[pb + 2];
            float b3 = B[pb + 3], b4 = B[pb + 4], b5 = B[pb + 5];
            float e0 = fmaf(D1, b0, fmaf(D3, b1, fmaf(D5, b2, D7 * b3)));
            float o0 = fmaf(D0, b0, fmaf(D2, b1, fmaf(D4, b2, D6 * b3)));
            float e1 = fmaf(D1, b1, fmaf(D3, b2, fmaf(D5, b3, D7 * b4)));
            float o1 = fmaf(D0, b1, fmaf(D2, b2, fmaf(D4, b3, D6 * b4)));
            float e2 = fmaf(D1, b2, fmaf(D3, b3, fmaf(D5, b4, D7 * b5)));
            float y0 = fmaf(D1, e0, fmaf(D3, o0, fmaf(D5, e1, D7 * o1)));
            float y1 = fmaf(D0, e0, fmaf(D2, o0, fmaf(D4, e1, D6 * o1)));
            float y2 = fmaf(D1, o0, fmaf(D3, e1, fmaf(D5, o1, D7 * e2)));
            float y3 = fmaf(D0, o0, fmaf(D2, e1, fmaf(D4, o1, D6 * e2)));
            *reinterpret_cast<float4*>(A + 4 * pb) = make_float4(y0, y1, y2, y3);
        }
    }
    __syncthreads();

    // ---- Stage 4: fused synthesis levels 3+4 (t2 -> t3 in regs -> out),
    //      + season = x - trend. Quad ib in [0,4096): reads t2 local
    //      [ib..ib+5] (max 4100 <= 4103 written); global quad = h*4096 + ib.
    {
        const float4* x4  = reinterpret_cast<const float4*>(xr);
        float4* tr4 = reinterpret_cast<float4*>(trend  + (size_t)row * ROWLEN);
        float4* se4 = reinterpret_cast<float4*>(season + (size_t)row * ROWLEN);
        const int gq0 = h << 12;   // h * 4096
        for (int ib = tid; ib < 4096; ib += NTT) {
            float a0 = A[ib],     a1 = A[ib + 1], a2 = A[ib + 2];
            float a3 = A[ib + 3], a4 = A[ib + 4], a5 = A[ib + 5];
            float e0 = fmaf(D1, a0, fmaf(D3, a1, fmaf(D5, a2, D7 * a3)));
            float o0 = fmaf(D0, a0, fmaf(D2, a1, fmaf(D4, a2, D6 * a3)));
            float e1 = fmaf(D1, a1, fmaf(D3, a2, fmaf(D5, a3, D7 * a4)));
            float o1 = fmaf(D0, a1, fmaf(D2, a2, fmaf(D4, a3, D6 * a4)));
            float e2 = fmaf(D1, a2, fmaf(D3, a3, fmaf(D5, a4, D7 * a5)));
            float y0 = fmaf(D1, e0, fmaf(D3, o0, fmaf(D5, e1, D7 * o1)));
            float y1 = fmaf(D0, e0, fmaf(D2, o0, fmaf(D4, e1, D6 * o1)));
            float y2 = fmaf(D1, o0, fmaf(D3, e1, fmaf(D5, o1, D7 * e2)));
            float y3 = fmaf(D0, o0, fmaf(D2, e1, fmaf(D4, o1, D6 * e2)));
            const int gi = gq0 + ib;
            float4 xv = __ldg(&x4[gi]);
            tr4[gi] = make_float4(y0, y1, y2, y3);
            se4[gi] = make_float4(xv.x - y0, xv.y - y1, xv.z - y2, xv.w - y3);
        }
    }
}

extern "C" void kernel_launch(void* const* d_in, const int* in_sizes, int n_in,
                              void* d_out, int out_size)
{
    const float* x = (const float*)d_in[0];
    const int rows = in_sizes[0] / ROWLEN;   // 32 * 16 = 512 for this shape
    float* out = (float*)d_out;
    float* season = out;                                  // tuple element 0
    float* trend  = out + (size_t)rows * ROWLEN;          // tuple element 1

    cudaFuncSetAttribute(WT_series_decomp_kernel,
                         cudaFuncAttributeMaxDynamicSharedMemorySize, SMEM_BYTES);
    WT_series_decomp_kernel<<<rows * 2, NTT, SMEM_BYTES>>>(x, season, trend);
}